// round 4
// baseline (speedup 1.0000x reference)
#include <cuda_runtime.h>
#include <cstdint>

// GraphAttention: out[b,t,:] = LayerNorm(node + sum_k att_k * neigh_k)
//   att_k = dot(neigh_k, node)/15, neigh_k masked (0/1).
// Inputs: node_ids i32[B*3], neighbor_ids i32[B*3*64], neighbor_mask i32[B*3*64],
//         emb f32[500000*128], gamma f32[128], beta f32[128]. Output f32[B*3*128].

#define DDIM  128
#define KNB   64
#define NWARP 4
#define KPW   (KNB / NWARP)   // 16 neighbors per warp

#define CP_ASYNC_16(dst_u32, gptr) \
    asm volatile("cp.async.cg.shared.global [%0], [%1], 16;" :: "r"(dst_u32), "l"(gptr))
#define CP_COMMIT()  asm volatile("cp.async.commit_group;" ::: "memory")
#define CP_WAIT(n)   asm volatile("cp.async.wait_group %0;" :: "n"(n) : "memory")

__global__ __launch_bounds__(128, 6)
void ga_kernel(const int* __restrict__ node_ids,
               const int* __restrict__ nbr_ids,
               const int* __restrict__ nbr_mask,
               const float* __restrict__ emb,
               const float* __restrict__ gamma,
               const float* __restrict__ beta,
               float* __restrict__ out,
               int n_rows)
{
    const int bt = blockIdx.x;
    if (bt >= n_rows) return;

    const int tid = threadIdx.x;
    const int w   = tid >> 5;
    const int l   = tid & 31;

    __shared__ float4 srow[NWARP][KPW][32];   // 32 KB row-staging buffer
    __shared__ float  sacc[NWARP][DDIM];
    __shared__ float  sred[2 * NWARP];
    __shared__ int    slist[NWARP][KPW];

    // Node row: lane l holds dims [4l, 4l+4)
    const size_t nid = (size_t)node_ids[bt];
    const float4 n4 = reinterpret_cast<const float4*>(emb + nid * DDIM)[l];

    const int* kid = nbr_ids  + (size_t)bt * KNB + w * KPW;
    const int* km  = nbr_mask + (size_t)bt * KNB + w * KPW;

    // ---- Warp compaction of unmasked neighbor ids into a dense smem list ----
    int myid = 0, mym = 0;
    if (l < KPW) { mym = __ldg(km + l); myid = __ldg(kid + l); }
    const unsigned bal = __ballot_sync(0xffffffffu, mym != 0);
    const int cnt = __popc(bal);
    const int pos = __popc(bal & ((1u << l) - 1u));
    if (mym) slist[w][pos] = myid;
    // Pad to a multiple of 8 with the node id (L2-hot, weight forced to 0).
    const int cnt_pad = (cnt + 7) & ~7;
    if (l >= cnt && l < cnt_pad) slist[w][l] = (int)nid;
    __syncwarp();

    // ---- Stage all rows via cp.async: up to 16 row-loads in flight per warp ----
    const int nstages = cnt_pad >> 3;         // 0, 1, or 2 stages of 8 rows
    if (nstages >= 1) {
        #pragma unroll
        for (int j = 0; j < 8; j++) {
            const float4* g = reinterpret_cast<const float4*>(
                                  emb + (size_t)slist[w][j] * DDIM) + l;
            uint32_t dst = (uint32_t)__cvta_generic_to_shared(&srow[w][j][l]);
            CP_ASYNC_16(dst, g);
        }
        CP_COMMIT();
    }
    if (nstages == 2) {
        #pragma unroll
        for (int j = 8; j < 16; j++) {
            const float4* g = reinterpret_cast<const float4*>(
                                  emb + (size_t)slist[w][j] * DDIM) + l;
            uint32_t dst = (uint32_t)__cvta_generic_to_shared(&srow[w][j][l]);
            CP_ASYNC_16(dst, g);
        }
        CP_COMMIT();
    }

    float4 acc = make_float4(0.f, 0.f, 0.f, 0.f);

    // Process one 8-row stage: two sub-groups of 4 interleaved butterfly chains.
    #define PROC4(jb)                                                          \
    {                                                                          \
        float4 v0 = srow[w][(jb) + 0][l];                                      \
        float4 v1 = srow[w][(jb) + 1][l];                                      \
        float4 v2 = srow[w][(jb) + 2][l];                                      \
        float4 v3 = srow[w][(jb) + 3][l];                                      \
        float p0 = n4.x*v0.x + n4.y*v0.y + n4.z*v0.z + n4.w*v0.w;              \
        float p1 = n4.x*v1.x + n4.y*v1.y + n4.z*v1.z + n4.w*v1.w;              \
        float p2 = n4.x*v2.x + n4.y*v2.y + n4.z*v2.z + n4.w*v2.w;              \
        float p3 = n4.x*v3.x + n4.y*v3.y + n4.z*v3.z + n4.w*v3.w;              \
        _Pragma("unroll")                                                      \
        for (int off = 16; off > 0; off >>= 1) {                               \
            p0 += __shfl_xor_sync(0xffffffffu, p0, off);                       \
            p1 += __shfl_xor_sync(0xffffffffu, p1, off);                       \
            p2 += __shfl_xor_sync(0xffffffffu, p2, off);                       \
            p3 += __shfl_xor_sync(0xffffffffu, p3, off);                       \
        }                                                                      \
        const float a0 = ((jb) + 0 < cnt) ? p0 * (1.0f / 15.0f) : 0.f;         \
        const float a1 = ((jb) + 1 < cnt) ? p1 * (1.0f / 15.0f) : 0.f;         \
        const float a2 = ((jb) + 2 < cnt) ? p2 * (1.0f / 15.0f) : 0.f;         \
        const float a3 = ((jb) + 3 < cnt) ? p3 * (1.0f / 15.0f) : 0.f;         \
        acc.x = fmaf(a0, v0.x, fmaf(a1, v1.x, fmaf(a2, v2.x, fmaf(a3, v3.x, acc.x)))); \
        acc.y = fmaf(a0, v0.y, fmaf(a1, v1.y, fmaf(a2, v2.y, fmaf(a3, v3.y, acc.y)))); \
        acc.z = fmaf(a0, v0.z, fmaf(a1, v1.z, fmaf(a2, v2.z, fmaf(a3, v3.z, acc.z)))); \
        acc.w = fmaf(a0, v0.w, fmaf(a1, v1.w, fmaf(a2, v2.w, fmaf(a3, v3.w, acc.w)))); \
    }

    if (nstages >= 1) {
        if (nstages == 2) { CP_WAIT(1); } else { CP_WAIT(0); }
        PROC4(0); PROC4(4);
    }
    if (nstages == 2) {
        CP_WAIT(0);
        PROC4(8); PROC4(12);
    }
    #undef PROC4

    reinterpret_cast<float4*>(&sacc[w][0])[l] = acc;
    __syncthreads();

    // Thread tid owns dim d = tid.
    const int d = tid;
    const float nd = __ldg(emb + nid * DDIM + d);   // L1/L2 hit (row already fetched)
    float x = nd + sacc[0][d] + sacc[1][d] + sacc[2][d] + sacc[3][d];

    // Block-level LayerNorm reduction over 128 values
    float s = x, s2 = x * x;
    #pragma unroll
    for (int off = 16; off > 0; off >>= 1) {
        s  += __shfl_xor_sync(0xffffffffu, s,  off);
        s2 += __shfl_xor_sync(0xffffffffu, s2, off);
    }
    if (l == 0) { sred[w] = s; sred[NWARP + w] = s2; }
    __syncthreads();

    s  = sred[0] + sred[1] + sred[2] + sred[3];
    s2 = sred[NWARP + 0] + sred[NWARP + 1] + sred[NWARP + 2] + sred[NWARP + 3];

    const float mu  = s * (1.0f / DDIM);
    const float var = s2 * (1.0f / DDIM) - mu * mu;
    const float inv = rsqrtf(var + 1e-5f);

    out[(size_t)bt * DDIM + d] = (x - mu) * inv * gamma[d] + beta[d];
}

extern "C" void kernel_launch(void* const* d_in, const int* in_sizes, int n_in,
                              void* d_out, int out_size)
{
    const int*   node_ids = (const int*)  d_in[0];
    const int*   nbr_ids  = (const int*)  d_in[1];
    const int*   nbr_mask = (const int*)  d_in[2];
    const float* emb      = (const float*)d_in[3];
    const float* gamma    = (const float*)d_in[4];
    const float* beta     = (const float*)d_in[5];
    float*       out      = (float*)d_out;

    const int n_rows = in_sizes[0];          // B*3 = 12288
    ga_kernel<<<n_rows, 128>>>(node_ids, nbr_ids, nbr_mask, emb, gamma, beta,
                               out, n_rows);
}

// round 5
// speedup vs baseline: 1.1916x; 1.1916x over previous
#include <cuda_runtime.h>
#include <cstdint>

// GraphAttention: out[b,t,:] = LayerNorm(node + sum_k att_k * neigh_k)
//   att_k = dot(neigh_k, node)/15, neigh_k masked (0/1).
// Inputs: node_ids i32[B*3], neighbor_ids i32[B*3*64], neighbor_mask i32[B*3*64],
//         emb f32[500000*128], gamma f32[128], beta f32[128]. Output f32[B*3*128].

#define DDIM  128
#define KNB   64
#define NWARP 4
#define KPW   (KNB / NWARP)   // 16 neighbors per warp

__global__ __launch_bounds__(128, 8)
void ga_kernel(const int* __restrict__ node_ids,
               const int* __restrict__ nbr_ids,
               const int* __restrict__ nbr_mask,
               const float* __restrict__ emb,
               const float* __restrict__ gamma,
               const float* __restrict__ beta,
               float* __restrict__ out,
               int n_rows)
{
    const int bt = blockIdx.x;
    if (bt >= n_rows) return;

    const int tid = threadIdx.x;
    const int w   = tid >> 5;
    const int l   = tid & 31;

    __shared__ float sacc[NWARP][DDIM];
    __shared__ float sred[2 * NWARP];
    __shared__ int   slist[NWARP][KPW];

    // Node row: lane l holds dims [4l, 4l+4)
    const size_t nid = (size_t)node_ids[bt];
    const float4 n4 = reinterpret_cast<const float4*>(emb + nid * DDIM)[l];

    const int* kid = nbr_ids  + (size_t)bt * KNB + w * KPW;
    const int* km  = nbr_mask + (size_t)bt * KNB + w * KPW;

    // ---- Warp compaction of unmasked neighbor ids into a dense smem list ----
    int myid = 0, mym = 0;
    if (l < KPW) { mym = __ldg(km + l); myid = __ldg(kid + l); }
    const unsigned bal = __ballot_sync(0xffffffffu, mym != 0);
    const int cnt = __popc(bal);
    const int pos = __popc(bal & ((1u << l) - 1u));
    if (mym) slist[w][pos] = myid;
    // Pad the ENTIRE remainder with the node id: valid addresses for prefetch,
    // L2-hot rows for the padded LDGs, weight forced to 0 later.
    if (l >= cnt && l < KPW) slist[w][l] = (int)nid;
    __syncwarp();

    // ---- Fire-and-forget L2 prefetch of all 16 rows (2 instrs, 64 lines) ----
    // Lane l prefetches 128B line (l&3) of row (l>>2) and row 8+(l>>2).
    {
        const int pr = l >> 2;
        const int po = (l & 3) * 32;              // 32 floats = 128 B
        const float* pa0 = emb + (size_t)slist[w][pr]     * DDIM + po;
        const float* pa1 = emb + (size_t)slist[w][8 + pr] * DDIM + po;
        asm volatile("prefetch.global.L2 [%0];" :: "l"(pa0));
        asm volatile("prefetch.global.L2 [%0];" :: "l"(pa1));
    }

    float4 acc = make_float4(0.f, 0.f, 0.f, 0.f);
    const int cnt_pad = (cnt + 3) & ~3;
    const int groups  = cnt_pad >> 2;

    #define ROW(j) (reinterpret_cast<const float4*>(emb + (size_t)slist[w][(j)] * DDIM)[l])

    float4 v0, v1, v2, v3;
    if (groups > 0) {
        v0 = ROW(0); v1 = ROW(1); v2 = ROW(2); v3 = ROW(3);
    }

    for (int g = 0; g < groups; g++) {
        // Issue next group's 4 independent row loads before touching this group.
        float4 u0 = v0, u1 = v1, u2 = v2, u3 = v3;
        if (g + 1 < groups) {
            const int j = 4 * (g + 1);
            u0 = ROW(j + 0); u1 = ROW(j + 1); u2 = ROW(j + 2); u3 = ROW(j + 3);
        }

        // 4 independent dot products -> 4 interleaved butterfly chains.
        float p0 = n4.x*v0.x + n4.y*v0.y + n4.z*v0.z + n4.w*v0.w;
        float p1 = n4.x*v1.x + n4.y*v1.y + n4.z*v1.z + n4.w*v1.w;
        float p2 = n4.x*v2.x + n4.y*v2.y + n4.z*v2.z + n4.w*v2.w;
        float p3 = n4.x*v3.x + n4.y*v3.y + n4.z*v3.z + n4.w*v3.w;
        #pragma unroll
        for (int off = 16; off > 0; off >>= 1) {
            p0 += __shfl_xor_sync(0xffffffffu, p0, off);
            p1 += __shfl_xor_sync(0xffffffffu, p1, off);
            p2 += __shfl_xor_sync(0xffffffffu, p2, off);
            p3 += __shfl_xor_sync(0xffffffffu, p3, off);
        }
        const int jb = 4 * g;
        const float a0 = (jb + 0 < cnt) ? p0 * (1.0f / 15.0f) : 0.f;
        const float a1 = (jb + 1 < cnt) ? p1 * (1.0f / 15.0f) : 0.f;
        const float a2 = (jb + 2 < cnt) ? p2 * (1.0f / 15.0f) : 0.f;
        const float a3 = (jb + 3 < cnt) ? p3 * (1.0f / 15.0f) : 0.f;

        acc.x = fmaf(a0, v0.x, fmaf(a1, v1.x, fmaf(a2, v2.x, fmaf(a3, v3.x, acc.x))));
        acc.y = fmaf(a0, v0.y, fmaf(a1, v1.y, fmaf(a2, v2.y, fmaf(a3, v3.y, acc.y))));
        acc.z = fmaf(a0, v0.z, fmaf(a1, v1.z, fmaf(a2, v2.z, fmaf(a3, v3.z, acc.z))));
        acc.w = fmaf(a0, v0.w, fmaf(a1, v1.w, fmaf(a2, v2.w, fmaf(a3, v3.w, acc.w))));

        v0 = u0; v1 = u1; v2 = u2; v3 = u3;
    }
    #undef ROW

    reinterpret_cast<float4*>(&sacc[w][0])[l] = acc;
    __syncthreads();

    // Thread tid owns dim d = tid.
    const int d = tid;
    const float nd = __ldg(emb + nid * DDIM + d);   // L1/L2 hit (row already fetched)
    float x = nd + sacc[0][d] + sacc[1][d] + sacc[2][d] + sacc[3][d];

    // Block-level LayerNorm reduction over 128 values
    float s = x, s2 = x * x;
    #pragma unroll
    for (int off = 16; off > 0; off >>= 1) {
        s  += __shfl_xor_sync(0xffffffffu, s,  off);
        s2 += __shfl_xor_sync(0xffffffffu, s2, off);
    }
    if (l == 0) { sred[w] = s; sred[NWARP + w] = s2; }
    __syncthreads();

    s  = sred[0] + sred[1] + sred[2] + sred[3];
    s2 = sred[NWARP + 0] + sred[NWARP + 1] + sred[NWARP + 2] + sred[NWARP + 3];

    const float mu  = s * (1.0f / DDIM);
    const float var = s2 * (1.0f / DDIM) - mu * mu;
    const float inv = rsqrtf(var + 1e-5f);

    out[(size_t)bt * DDIM + d] = (x - mu) * inv * gamma[d] + beta[d];
}

extern "C" void kernel_launch(void* const* d_in, const int* in_sizes, int n_in,
                              void* d_out, int out_size)
{
    const int*   node_ids = (const int*)  d_in[0];
    const int*   nbr_ids  = (const int*)  d_in[1];
    const int*   nbr_mask = (const int*)  d_in[2];
    const float* emb      = (const float*)d_in[3];
    const float* gamma    = (const float*)d_in[4];
    const float* beta     = (const float*)d_in[5];
    float*       out      = (float*)d_out;

    const int n_rows = in_sizes[0];          // B*3 = 12288
    ga_kernel<<<n_rows, 128>>>(node_ids, nbr_ids, nbr_mask, emb, gamma, beta,
                               out, n_rows);
}